// round 3
// baseline (speedup 1.0000x reference)
#include <cuda_runtime.h>
#include <cstdint>

#define NN 100000
#define NE 1600000
#define NG 512
#define D  50
#define DE 8
#define DZ 108
#define NOUT 10

// ---------------- device scratch (no runtime allocation allowed) ----------------
// Projection table P[n][200] = [Af(50) | Bf(50) | As(50) | Bs(50)], biases folded
// into Af/As.  80 MB — mostly L2-resident during the edge kernel.
__device__ __align__(16) float g_P[(size_t)NN * 200];
__device__ __align__(16) float g_msg[(size_t)NN * D];   // scatter accumulator
__device__ __align__(16) float g_h0[(size_t)NN * D];    // ping-pong h buffers
__device__ __align__(16) float g_h1[(size_t)NN * D];
__device__ float g_poolmax[NG * D];
__device__ float g_poolsum[NG * D];
__device__ int   g_cnt[NG];
__device__ float g_enc[NG * 2 * D];

constexpr float kL2E = 1.4426950408889634f;   // log2(e)
constexpr float kLN2 = 0.6931471805599453f;   // ln(2)

__device__ __forceinline__ float fast_ex2(float x){ float y; asm("ex2.approx.ftz.f32 %0, %1;" : "=f"(y) : "f"(x)); return y; }
__device__ __forceinline__ float fast_lg2(float x){ float y; asm("lg2.approx.ftz.f32 %0, %1;" : "=f"(y) : "f"(x)); return y; }
__device__ __forceinline__ float fast_rcp(float x){ float y; asm("rcp.approx.ftz.f32 %0, %1;" : "=f"(y) : "f"(x)); return y; }

// sigmoid(x) = 1 / (1 + 2^(-x*log2e))
__device__ __forceinline__ float sigm(float x){
  return fast_rcp(1.0f + fast_ex2(-x * kL2E));
}
// softplus(x) = max(x,0) + ln2 * log2(1 + 2^(-|x|*log2e))
__device__ __forceinline__ float softp(float x){
  float t = fast_ex2(-fabsf(x) * kL2E);
  return fmaxf(x, 0.0f) + kLN2 * fast_lg2(1.0f + t);
}

// In-device ping-pong selection (layer: 0 -> x->h0, 1 -> h0->h1, 2 -> h1->h0)
__device__ __forceinline__ const float* layer_in(const float* x, int layer){
  if (layer == 0) return x;
  if (layer == 1) return g_h0;
  return g_h1;
}
__device__ __forceinline__ float* layer_out(int layer){
  return (layer == 1) ? g_h1 : g_h0;
}

// ---------------- setup / zero kernels ----------------
__global__ void zero_global_bufs(){
  int i = blockIdx.x * blockDim.x + threadIdx.x;
  int stride = gridDim.x * blockDim.x;
  for (int j = i; j < NG * 2 * D; j += stride) g_enc[j] = 0.0f;
  if (i < NG) g_cnt[i] = 0;
}

__global__ void count_kernel(const int* __restrict__ batch){
  int i = blockIdx.x * blockDim.x + threadIdx.x;
  if (i < NN) atomicAdd(&g_cnt[batch[i]], 1);
}

__global__ void zero_layer_bufs(){
  int i = blockIdx.x * blockDim.x + threadIdx.x;
  int stride = gridDim.x * blockDim.x;
  float4 z = make_float4(0.f, 0.f, 0.f, 0.f);
  float4* m4 = reinterpret_cast<float4*>(g_msg);
  const int nm4 = (NN * D) / 4;   // 1,250,000
  for (int j = i; j < nm4; j += stride) m4[j] = z;
  for (int j = i; j < NG * D; j += stride){ g_poolmax[j] = 0.0f; g_poolsum[j] = 0.0f; }
}

// ---------------- node projection: P[n] = [W blocks] @ h[n] (+bias) ----------------
// One thread per node, 200 outputs per thread.  Weights staged in smem, 16B reads.
__global__ void __launch_bounds__(128) proj_kernel(
    const float* __restrict__ x, int layer,
    const float* __restrict__ Wf, const float* __restrict__ Ws,
    const float* __restrict__ bf, const float* __restrict__ bs){
  // Wsm row r (0..199): r<50 -> Wf[r][0:50] ; r<100 -> Wf[r-50][50:100]
  //                     r<150 -> Ws[r-100][0:50] ; else Ws[r-150][50:100]
  __shared__ __align__(16) float Wsm[200][52];
  __shared__ float bsm[100];
  int t = threadIdx.x;
  for (int i = t; i < 200 * 52; i += blockDim.x){
    int r = i / 52, k = i - r * 52;
    float w = 0.0f;
    if (k < 50){
      if      (r <  50) w = Wf[ r        * DZ +      k];
      else if (r < 100) w = Wf[(r -  50) * DZ + 50 + k];
      else if (r < 150) w = Ws[(r - 100) * DZ +      k];
      else              w = Ws[(r - 150) * DZ + 50 + k];
    }
    Wsm[r][k] = w;
  }
  if (t < 50){ bsm[t] = bf[t]; bsm[50 + t] = bs[t]; }
  __syncthreads();

  int n = blockIdx.x * blockDim.x + t;
  if (n >= NN) return;

  const float* h = layer_in(x, layer);
  float hr[52];
  const float2* hp = reinterpret_cast<const float2*>(h + (size_t)n * D);
  #pragma unroll
  for (int i = 0; i < 25; i++){ float2 v = hp[i]; hr[2*i] = v.x; hr[2*i+1] = v.y; }
  hr[50] = 0.0f; hr[51] = 0.0f;

  float* out = g_P + (size_t)n * 200;
  for (int r0 = 0; r0 < 200; r0 += 4){
    float a0 = 0.f, a1 = 0.f, a2 = 0.f, a3 = 0.f;
    #pragma unroll
    for (int k = 0; k < 52; k += 4){
      float4 w0 = *reinterpret_cast<const float4*>(&Wsm[r0 + 0][k]);
      float4 w1 = *reinterpret_cast<const float4*>(&Wsm[r0 + 1][k]);
      float4 w2 = *reinterpret_cast<const float4*>(&Wsm[r0 + 2][k]);
      float4 w3 = *reinterpret_cast<const float4*>(&Wsm[r0 + 3][k]);
      a0 += w0.x*hr[k] + w0.y*hr[k+1] + w0.z*hr[k+2] + w0.w*hr[k+3];
      a1 += w1.x*hr[k] + w1.y*hr[k+1] + w1.z*hr[k+2] + w1.w*hr[k+3];
      a2 += w2.x*hr[k] + w2.y*hr[k+1] + w2.z*hr[k+2] + w2.w*hr[k+3];
      a3 += w3.x*hr[k] + w3.y*hr[k+1] + w3.z*hr[k+2] + w3.w*hr[k+3];
    }
    // fold biases: rows [0,50) get bf, rows [100,150) get bs
    auto bias_of = [&](int r) -> float {
      if (r < 50) return bsm[r];
      if (r >= 100 && r < 150) return bsm[r - 50];
      return 0.0f;
    };
    float4 res = make_float4(a0 + bias_of(r0+0), a1 + bias_of(r0+1),
                             a2 + bias_of(r0+2), a3 + bias_of(r0+3));
    *reinterpret_cast<float4*>(out + r0) = res;
  }
}

// ---------------- edge kernel: gather-gate-scatter ----------------
// 250 active threads/block = 10 edges × 25 channel-pairs. Thread handles channels
// (2p, 2p+1), so its edge-attr weights live permanently in registers and the
// scatter is one vectorized float2 atomicAdd (RED.ADD.64) per thread.
__global__ void __launch_bounds__(256) edge_kernel(
    const int* __restrict__ ei, const float* __restrict__ ea,
    const float* __restrict__ Wf, const float* __restrict__ Ws){
  int t = threadIdx.x;
  if (t >= 250) return;
  int p  = t % 25;
  int c0 = 2 * p;

  float wf0[8], wf1[8], ws0[8], ws1[8];
  #pragma unroll
  for (int k = 0; k < 8; k++){
    wf0[k] = Wf[ c0      * DZ + 100 + k];
    wf1[k] = Wf[(c0 + 1) * DZ + 100 + k];
    ws0[k] = Ws[ c0      * DZ + 100 + k];
    ws1[k] = Ws[(c0 + 1) * DZ + 100 + k];
  }

  int e = blockIdx.x * 10 + t / 25;
  const int estride = gridDim.x * 10;
  for (; e < NE; e += estride){
    int si = __ldg(ei + e);
    int di = __ldg(ei + NE + e);
    const float* Pd = g_P + (size_t)di * 200;
    const float* Ps = g_P + (size_t)si * 200;
    float2 af  = *reinterpret_cast<const float2*>(Pd +       c0);
    float2 as2 = *reinterpret_cast<const float2*>(Pd + 100 + c0);
    float2 bf2 = *reinterpret_cast<const float2*>(Ps +  50 + c0);
    float2 bs2 = *reinterpret_cast<const float2*>(Ps + 150 + c0);
    float4 e0 = *reinterpret_cast<const float4*>(ea + (size_t)e * 8);
    float4 e1 = *reinterpret_cast<const float4*>(ea + (size_t)e * 8 + 4);

    float f0 = af.x + bf2.x
             + wf0[0]*e0.x + wf0[1]*e0.y + wf0[2]*e0.z + wf0[3]*e0.w
             + wf0[4]*e1.x + wf0[5]*e1.y + wf0[6]*e1.z + wf0[7]*e1.w;
    float f1 = af.y + bf2.y
             + wf1[0]*e0.x + wf1[1]*e0.y + wf1[2]*e0.z + wf1[3]*e0.w
             + wf1[4]*e1.x + wf1[5]*e1.y + wf1[6]*e1.z + wf1[7]*e1.w;
    float g0 = as2.x + bs2.x
             + ws0[0]*e0.x + ws0[1]*e0.y + ws0[2]*e0.z + ws0[3]*e0.w
             + ws0[4]*e1.x + ws0[5]*e1.y + ws0[6]*e1.z + ws0[7]*e1.w;
    float g1 = as2.y + bs2.y
             + ws1[0]*e0.x + ws1[1]*e0.y + ws1[2]*e0.z + ws1[3]*e0.w
             + ws1[4]*e1.x + ws1[5]*e1.y + ws1[6]*e1.z + ws1[7]*e1.w;

    float2 m = make_float2(sigm(f0) * softp(g0), sigm(f1) * softp(g1));

    // offset (di*50 + c0) is even -> 8B-aligned; native float2 red on sm_90+
    atomicAdd(reinterpret_cast<float2*>(g_msg + (size_t)di * D + c0), m);
  }
}

// ---------------- finalize: residual + ReLU + pooled max/sum ----------------
__global__ void finalize_kernel(const float* __restrict__ x, int layer,
                                const int* __restrict__ batch){
  const float* h_in = layer_in(x, layer);
  float* h_out = layer_out(layer);
  int i = blockIdx.x * blockDim.x + threadIdx.x;
  int stride = gridDim.x * blockDim.x;
  for (; i < NN * D; i += stride){
    int n = i / D;
    int c = i - n * D;
    float v = g_msg[i] + h_in[i];
    v = fmaxf(v, 0.0f);
    h_out[i] = v;
    int b = batch[n];
    // v >= 0 and poolmax initialized to 0.0f (bits 0): int-max == float-max
    atomicMax(reinterpret_cast<int*>(&g_poolmax[b * D + c]), __float_as_int(v));
    atomicAdd(&g_poolsum[b * D + c], v);
  }
}

__global__ void acc_enc_kernel(){
  int i = blockIdx.x * blockDim.x + threadIdx.x;
  if (i >= NG * D) return;
  int b = i / D, c = i - b * D;
  g_enc[b * 100 + c]      += g_poolmax[i];
  g_enc[b * 100 + 50 + c] += g_poolsum[i] / fmaxf((float)g_cnt[b], 1.0f);
}

// ---------------- head: linear + log_softmax; emit [logp | enc] ----------------
__global__ void head_kernel(const float* __restrict__ lw, const float* __restrict__ lb,
                            float* __restrict__ out, int out_size){
  int b = blockIdx.x * blockDim.x + threadIdx.x;
  if (b >= NG) return;
  float e[100];
  #pragma unroll
  for (int k = 0; k < 100; k++) e[k] = g_enc[b * 100 + k];
  float lg[NOUT];
  #pragma unroll
  for (int j = 0; j < NOUT; j++){
    float acc = lb[j];
    #pragma unroll
    for (int k = 0; k < 100; k++) acc += e[k] * lw[j * 100 + k];
    lg[j] = acc;
  }
  float mx = lg[0];
  #pragma unroll
  for (int j = 1; j < NOUT; j++) mx = fmaxf(mx, lg[j]);
  float ss = 0.0f;
  #pragma unroll
  for (int j = 0; j < NOUT; j++) ss += fast_ex2((lg[j] - mx) * kL2E);
  float lse = mx + kLN2 * fast_lg2(ss);
  #pragma unroll
  for (int j = 0; j < NOUT; j++) out[b * NOUT + j] = lg[j] - lse;
  if (out_size >= NG * NOUT + NG * 100){
    #pragma unroll 4
    for (int k = 0; k < 100; k++) out[NG * NOUT + b * 100 + k] = e[k];
  }
}

// ---------------- launch (pure kernel launches; graph-capture safe) ----------------
extern "C" void kernel_launch(void* const* d_in, const int* in_sizes, int n_in,
                              void* d_out, int out_size){
  (void)in_sizes; (void)n_in;
  const float* x  = (const float*)d_in[0];
  const int*   ei = (const int*)  d_in[1];
  const float* ea = (const float*)d_in[2];
  const int*   bt = (const int*)  d_in[3];
  const float* Wf = (const float*)d_in[4];
  const float* bf = (const float*)d_in[5];
  const float* Ws = (const float*)d_in[6];
  const float* bs = (const float*)d_in[7];
  const float* lw = (const float*)d_in[8];
  const float* lb = (const float*)d_in[9];
  float* out = (float*)d_out;

  zero_global_bufs<<<64, 256>>>();
  count_kernel<<<(NN + 255) / 256, 256>>>(bt);

  for (int i = 0; i < 3; i++){
    zero_layer_bufs<<<2048, 256>>>();
    proj_kernel<<<(NN + 127) / 128, 128>>>(x, i, Wf + i * D * DZ, Ws + i * D * DZ,
                                           bf + i * D, bs + i * D);
    edge_kernel<<<1024, 256>>>(ei, ea, Wf + i * D * DZ, Ws + i * D * DZ);
    finalize_kernel<<<4096, 256>>>(x, i, bt);
    acc_enc_kernel<<<(NG * D + 255) / 256, 256>>>();
  }

  head_kernel<<<(NG + 127) / 128, 128>>>(lw, lb, out, out_size);
}

// round 4
// speedup vs baseline: 1.0984x; 1.0984x over previous
#include <cuda_runtime.h>
#include <cuda_fp16.h>
#include <cstdint>

#define NN 100000
#define NE 1600000
#define NG 512
#define D  50
#define DE 8
#define DZ 108
#define NOUT 10

// ---------------- device scratch (no runtime allocation allowed) ----------------
// Projection table Ph[n][200] (fp16) = [Af(50) | Bf(50) | As(50) | Bs(50)],
// biases folded into Af/As.  40 MB — L2-resident during the edge kernel.
__device__ __align__(16) __half g_Ph[(size_t)NN * 200];
__device__ __align__(16) float g_msg[(size_t)NN * D];   // scatter accumulator (stays zeroed between launches)
__device__ __align__(16) float g_h0[(size_t)NN * D];    // ping-pong h buffers
__device__ __align__(16) float g_h1[(size_t)NN * D];
__device__ float g_poolmax[NG * D];
__device__ float g_poolsum[NG * D];
__device__ int   g_cnt[NG];
__device__ float g_enc[NG * 2 * D];

constexpr float kL2E = 1.4426950408889634f;   // log2(e)
constexpr float kLN2 = 0.6931471805599453f;   // ln(2)

__device__ __forceinline__ float fast_ex2(float x){ float y; asm("ex2.approx.ftz.f32 %0, %1;" : "=f"(y) : "f"(x)); return y; }
__device__ __forceinline__ float fast_lg2(float x){ float y; asm("lg2.approx.ftz.f32 %0, %1;" : "=f"(y) : "f"(x)); return y; }
__device__ __forceinline__ float fast_rcp(float x){ float y; asm("rcp.approx.ftz.f32 %0, %1;" : "=f"(y) : "f"(x)); return y; }

__device__ __forceinline__ float sigm(float x){
  return fast_rcp(1.0f + fast_ex2(-x * kL2E));
}
__device__ __forceinline__ float softp(float x){
  float t = fast_ex2(-fabsf(x) * kL2E);
  return fmaxf(x, 0.0f) + kLN2 * fast_lg2(1.0f + t);
}

// In-device ping-pong selection (layer: 0 -> x->h0, 1 -> h0->h1, 2 -> h1->h0)
__device__ __forceinline__ const float* layer_in(const float* x, int layer){
  if (layer == 0) return x;
  if (layer == 1) return g_h0;
  return g_h1;
}
__device__ __forceinline__ float* layer_out(int layer){
  return (layer == 1) ? g_h1 : g_h0;
}

// ---------------- setup ----------------
__global__ void zero_global_bufs(){
  int i = blockIdx.x * blockDim.x + threadIdx.x;
  int stride = gridDim.x * blockDim.x;
  for (int j = i; j < NG * 2 * D; j += stride) g_enc[j] = 0.0f;
  for (int j = i; j < NG * D; j += stride){ g_poolmax[j] = 0.0f; g_poolsum[j] = 0.0f; }
  if (i < NG) g_cnt[i] = 0;
}

__global__ void count_kernel(const int* __restrict__ batch){
  int i = blockIdx.x * blockDim.x + threadIdx.x;
  if (i < NN) atomicAdd(&g_cnt[batch[i]], 1);
}

// ---------------- node projection: Ph[n] = [W blocks] @ h[n] (+bias), fp16 out ----
__global__ void __launch_bounds__(256) proj_kernel(
    const float* __restrict__ x, int layer,
    const float* __restrict__ Wf, const float* __restrict__ Ws,
    const float* __restrict__ bf, const float* __restrict__ bs){
  // Wsm row r (0..199): r<50 -> Wf[r][0:50] ; r<100 -> Wf[r-50][50:100]
  //                     r<150 -> Ws[r-100][0:50] ; else Ws[r-150][50:100]
  __shared__ __align__(16) float Wsm[200][52];
  __shared__ float bsm[100];
  int t = threadIdx.x;
  for (int i = t; i < 200 * 52; i += blockDim.x){
    int r = i / 52, k = i - r * 52;
    float w = 0.0f;
    if (k < 50){
      if      (r <  50) w = Wf[ r        * DZ +      k];
      else if (r < 100) w = Wf[(r -  50) * DZ + 50 + k];
      else if (r < 150) w = Ws[(r - 100) * DZ +      k];
      else              w = Ws[(r - 150) * DZ + 50 + k];
    }
    Wsm[r][k] = w;
  }
  if (t < 50){ bsm[t] = bf[t]; bsm[50 + t] = bs[t]; }
  __syncthreads();

  int n = blockIdx.x * blockDim.x + t;
  if (n >= NN) return;

  const float* h = layer_in(x, layer);
  float hr[52];
  const float2* hp = reinterpret_cast<const float2*>(h + (size_t)n * D);
  #pragma unroll
  for (int i = 0; i < 25; i++){ float2 v = hp[i]; hr[2*i] = v.x; hr[2*i+1] = v.y; }
  hr[50] = 0.0f; hr[51] = 0.0f;

  __half2* out = reinterpret_cast<__half2*>(g_Ph + (size_t)n * 200);
  for (int r0 = 0; r0 < 200; r0 += 4){
    float a0 = 0.f, a1 = 0.f, a2 = 0.f, a3 = 0.f;
    #pragma unroll
    for (int k = 0; k < 52; k += 4){
      float4 w0 = *reinterpret_cast<const float4*>(&Wsm[r0 + 0][k]);
      float4 w1 = *reinterpret_cast<const float4*>(&Wsm[r0 + 1][k]);
      float4 w2 = *reinterpret_cast<const float4*>(&Wsm[r0 + 2][k]);
      float4 w3 = *reinterpret_cast<const float4*>(&Wsm[r0 + 3][k]);
      a0 += w0.x*hr[k] + w0.y*hr[k+1] + w0.z*hr[k+2] + w0.w*hr[k+3];
      a1 += w1.x*hr[k] + w1.y*hr[k+1] + w1.z*hr[k+2] + w1.w*hr[k+3];
      a2 += w2.x*hr[k] + w2.y*hr[k+1] + w2.z*hr[k+2] + w2.w*hr[k+3];
      a3 += w3.x*hr[k] + w3.y*hr[k+1] + w3.z*hr[k+2] + w3.w*hr[k+3];
    }
    // fold biases: rows [0,50) get bf, rows [100,150) get bs
    auto bias_of = [&](int r) -> float {
      if (r < 50) return bsm[r];
      if (r >= 100 && r < 150) return bsm[r - 50];
      return 0.0f;
    };
    __half2 p0 = __floats2half2_rn(a0 + bias_of(r0+0), a1 + bias_of(r0+1));
    __half2 p1 = __floats2half2_rn(a2 + bias_of(r0+2), a3 + bias_of(r0+3));
    // r0 % 4 == 0 -> half2 index r0/2 is even -> 8B-aligned paired store
    *reinterpret_cast<uint2*>(out + r0 / 2) =
        make_uint2(*reinterpret_cast<uint32_t*>(&p0), *reinterpret_cast<uint32_t*>(&p1));
  }
}

// ---------------- edge kernel: gather-gate-scatter (fp16 gathers) ----------------
// 250 active threads/block = 10 edges × 25 channel-pairs. Thread handles channels
// (2p, 2p+1): edge-attr weights live in registers; gathers are 4B half2 loads;
// scatter is one vectorized float2 atomicAdd (RED.ADD.64) per thread.
__global__ void __launch_bounds__(256) edge_kernel(
    const int* __restrict__ ei, const float* __restrict__ ea,
    const float* __restrict__ Wf, const float* __restrict__ Ws){
  int t = threadIdx.x;
  if (t >= 250) return;
  int p  = t % 25;
  int c0 = 2 * p;

  float wf0[8], wf1[8], ws0[8], ws1[8];
  #pragma unroll
  for (int k = 0; k < 8; k++){
    wf0[k] = Wf[ c0      * DZ + 100 + k];
    wf1[k] = Wf[(c0 + 1) * DZ + 100 + k];
    ws0[k] = Ws[ c0      * DZ + 100 + k];
    ws1[k] = Ws[(c0 + 1) * DZ + 100 + k];
  }

  const __half2* Pbase = reinterpret_cast<const __half2*>(g_Ph);
  int e = blockIdx.x * 10 + t / 25;
  const int estride = gridDim.x * 10;
  for (; e < NE; e += estride){
    int si = __ldg(ei + e);
    int di = __ldg(ei + NE + e);
    const __half2* Pd = Pbase + (size_t)di * 100;
    const __half2* Ps = Pbase + (size_t)si * 100;
    float2 af  = __half22float2(Pd[     p]);   // Af  halves [0,50)
    float2 as2 = __half22float2(Pd[50 + p]);   // As  halves [100,150)
    float2 bf2 = __half22float2(Ps[25 + p]);   // Bf  halves [50,100)
    float2 bs2 = __half22float2(Ps[75 + p]);   // Bs  halves [150,200)
    float4 e0 = *reinterpret_cast<const float4*>(ea + (size_t)e * 8);
    float4 e1 = *reinterpret_cast<const float4*>(ea + (size_t)e * 8 + 4);

    float f0 = af.x + bf2.x
             + wf0[0]*e0.x + wf0[1]*e0.y + wf0[2]*e0.z + wf0[3]*e0.w
             + wf0[4]*e1.x + wf0[5]*e1.y + wf0[6]*e1.z + wf0[7]*e1.w;
    float f1 = af.y + bf2.y
             + wf1[0]*e0.x + wf1[1]*e0.y + wf1[2]*e0.z + wf1[3]*e0.w
             + wf1[4]*e1.x + wf1[5]*e1.y + wf1[6]*e1.z + wf1[7]*e1.w;
    float g0 = as2.x + bs2.x
             + ws0[0]*e0.x + ws0[1]*e0.y + ws0[2]*e0.z + ws0[3]*e0.w
             + ws0[4]*e1.x + ws0[5]*e1.y + ws0[6]*e1.z + ws0[7]*e1.w;
    float g1 = as2.y + bs2.y
             + ws1[0]*e0.x + ws1[1]*e0.y + ws1[2]*e0.z + ws1[3]*e0.w
             + ws1[4]*e1.x + ws1[5]*e1.y + ws1[6]*e1.z + ws1[7]*e1.w;

    float2 m = make_float2(sigm(f0) * softp(g0), sigm(f1) * softp(g1));
    atomicAdd(reinterpret_cast<float2*>(g_msg + (size_t)di * D + c0), m);
  }
}

// ---------------- finalize: residual + ReLU + smem-pooled max/sum ----------------
// batch is SORTED: a 10-node block usually spans 1-2 graphs. Pre-reduce into
// smem slots, flush once per (slot, channel). Also resets g_msg for next layer.
#define FN_NODES 10
#define FN_SLOTS 16
__global__ void __launch_bounds__(512) finalize_kernel(const float* __restrict__ x, int layer,
                                                       const int* __restrict__ batch){
  __shared__ float s_max[FN_SLOTS][50];
  __shared__ float s_sum[FN_SLOTS][50];
  __shared__ int s_bmin;
  __shared__ unsigned s_used;
  const float* h_in = layer_in(x, layer);
  float* h_out = layer_out(layer);
  int t = threadIdx.x;
  for (int i = t; i < FN_SLOTS * 50; i += 512){
    (&s_max[0][0])[i] = 0.0f; (&s_sum[0][0])[i] = 0.0f;
  }
  if (t == 0){
    int n0 = blockIdx.x * FN_NODES; if (n0 >= NN) n0 = NN - 1;
    s_bmin = batch[n0]; s_used = 0u;
  }
  __syncthreads();
  int bmin = s_bmin;

  if (t < FN_NODES * 50){
    int nl = t / 50, c = t - nl * 50;
    int n = blockIdx.x * FN_NODES + nl;
    if (n < NN){
      size_t i = (size_t)n * D + c;
      float v = fmaxf(g_msg[i] + h_in[i], 0.0f);
      h_out[i] = v;
      g_msg[i] = 0.0f;                       // reset for next layer / next launch
      int b = batch[n];
      int s = b - bmin;
      if ((unsigned)s < FN_SLOTS){
        atomicMax(reinterpret_cast<int*>(&s_max[s][c]), __float_as_int(v));
        atomicAdd(&s_sum[s][c], v);
        if (c == 0) atomicOr(&s_used, 1u << s);
      } else {
        atomicMax(reinterpret_cast<int*>(&g_poolmax[b * D + c]), __float_as_int(v));
        atomicAdd(&g_poolsum[b * D + c], v);
      }
    }
  }
  __syncthreads();
  unsigned used = s_used;
  for (int i = t; i < FN_SLOTS * 50; i += 512){
    int s = i / 50, c = i - s * 50;
    if (used & (1u << s)){
      int b = bmin + s;
      float mv = s_max[s][c];
      if (mv > 0.0f) atomicMax(reinterpret_cast<int*>(&g_poolmax[b * D + c]), __float_as_int(mv));
      float sv = s_sum[s][c];
      if (sv != 0.0f) atomicAdd(&g_poolsum[b * D + c], sv);
    }
  }
}

// accumulate pooled features into enc, re-zero pool buffers for next layer
__global__ void acc_enc_kernel(){
  int i = blockIdx.x * blockDim.x + threadIdx.x;
  if (i >= NG * D) return;
  int b = i / D, c = i - b * D;
  g_enc[b * 100 + c]      += g_poolmax[i];
  g_enc[b * 100 + 50 + c] += g_poolsum[i] / fmaxf((float)g_cnt[b], 1.0f);
  g_poolmax[i] = 0.0f;
  g_poolsum[i] = 0.0f;
}

// ---------------- head: linear + log_softmax; emit [logp | enc] ----------------
__global__ void head_kernel(const float* __restrict__ lw, const float* __restrict__ lb,
                            float* __restrict__ out, int out_size){
  int b = blockIdx.x * blockDim.x + threadIdx.x;
  if (b >= NG) return;
  float e[100];
  #pragma unroll
  for (int k = 0; k < 100; k++) e[k] = g_enc[b * 100 + k];
  float lg[NOUT];
  #pragma unroll
  for (int j = 0; j < NOUT; j++){
    float acc = lb[j];
    #pragma unroll
    for (int k = 0; k < 100; k++) acc += e[k] * lw[j * 100 + k];
    lg[j] = acc;
  }
  float mx = lg[0];
  #pragma unroll
  for (int j = 1; j < NOUT; j++) mx = fmaxf(mx, lg[j]);
  float ss = 0.0f;
  #pragma unroll
  for (int j = 0; j < NOUT; j++) ss += fast_ex2((lg[j] - mx) * kL2E);
  float lse = mx + kLN2 * fast_lg2(ss);
  #pragma unroll
  for (int j = 0; j < NOUT; j++) out[b * NOUT + j] = lg[j] - lse;
  if (out_size >= NG * NOUT + NG * 100){
    #pragma unroll 4
    for (int k = 0; k < 100; k++) out[NG * NOUT + b * 100 + k] = e[k];
  }
}

// ---------------- launch (pure kernel launches; graph-capture safe) ----------------
extern "C" void kernel_launch(void* const* d_in, const int* in_sizes, int n_in,
                              void* d_out, int out_size){
  (void)in_sizes; (void)n_in;
  const float* x  = (const float*)d_in[0];
  const int*   ei = (const int*)  d_in[1];
  const float* ea = (const float*)d_in[2];
  const int*   bt = (const int*)  d_in[3];
  const float* Wf = (const float*)d_in[4];
  const float* bf = (const float*)d_in[5];
  const float* Ws = (const float*)d_in[6];
  const float* bs = (const float*)d_in[7];
  const float* lw = (const float*)d_in[8];
  const float* lb = (const float*)d_in[9];
  float* out = (float*)d_out;

  zero_global_bufs<<<128, 256>>>();
  count_kernel<<<(NN + 255) / 256, 256>>>(bt);

  for (int i = 0; i < 3; i++){
    proj_kernel<<<(NN + 255) / 256, 256>>>(x, i, Wf + i * D * DZ, Ws + i * D * DZ,
                                           bf + i * D, bs + i * D);
    edge_kernel<<<1024, 256>>>(ei, ea, Wf + i * D * DZ, Ws + i * D * DZ);
    finalize_kernel<<<(NN + FN_NODES - 1) / FN_NODES, 512>>>(x, i, bt);
    acc_enc_kernel<<<(NG * D + 255) / 256, 256>>>();
  }

  head_kernel<<<(NG + 127) / 128, 128>>>(lw, lb, out, out_size);
}

// round 5
// speedup vs baseline: 1.6551x; 1.5068x over previous
#include <cuda_runtime.h>
#include <cuda_fp16.h>
#include <cstdint>

#define NN 100000
#define NE 1600000
#define NG 512
#define D  50
#define DE 8
#define DZ 108
#define NOUT 10

// ---------------- device scratch (no runtime allocation allowed) ----------------
// Projection table Ph[n][200] (fp16), interleaved per channel-pair p (p=0..24):
//   halves [4p .. 4p+3]       = Af[2p], Af[2p+1], As[2p], As[2p+1]   (dst part, biases folded)
//   halves [100+4p .. 100+4p+3] = Bf[2p], Bf[2p+1], Bs[2p], Bs[2p+1] (src part)
__device__ __align__(16) __half g_Ph[(size_t)NN * 200];
__device__ __align__(16) float g_msg[(size_t)NN * D];   // scatter accumulator (kept zeroed between launches)
__device__ __align__(16) float g_h0[(size_t)NN * D];    // ping-pong h buffers
__device__ __align__(16) float g_h1[(size_t)NN * D];
__device__ float g_poolmax[NG * D];
__device__ float g_poolsum[NG * D];
__device__ int   g_cnt[NG];
__device__ float g_enc[NG * 2 * D];

constexpr float kL2E = 1.4426950408889634f;   // log2(e)
constexpr float kLN2 = 0.6931471805599453f;   // ln(2)

__device__ __forceinline__ float fast_ex2(float x){ float y; asm("ex2.approx.ftz.f32 %0, %1;" : "=f"(y) : "f"(x)); return y; }
__device__ __forceinline__ float fast_lg2(float x){ float y; asm("lg2.approx.ftz.f32 %0, %1;" : "=f"(y) : "f"(x)); return y; }
__device__ __forceinline__ float fast_rcp(float x){ float y; asm("rcp.approx.ftz.f32 %0, %1;" : "=f"(y) : "f"(x)); return y; }

__device__ __forceinline__ float sigm(float x){
  return fast_rcp(1.0f + fast_ex2(-x * kL2E));
}
__device__ __forceinline__ float softp(float x){
  float t = fast_ex2(-fabsf(x) * kL2E);
  return fmaxf(x, 0.0f) + kLN2 * fast_lg2(1.0f + t);
}

__device__ __forceinline__ __half2 u2h(uint32_t u){ return *reinterpret_cast<__half2*>(&u); }

// In-device ping-pong selection (layer: 0 -> x->h0, 1 -> h0->h1, 2 -> h1->h0)
__device__ __forceinline__ const float* layer_in(const float* x, int layer){
  if (layer == 0) return x;
  if (layer == 1) return g_h0;
  return g_h1;
}
__device__ __forceinline__ float* layer_out(int layer){
  return (layer == 1) ? g_h1 : g_h0;
}

// ---------------- setup ----------------
__global__ void zero_global_bufs(){
  int i = blockIdx.x * blockDim.x + threadIdx.x;
  int stride = gridDim.x * blockDim.x;
  for (int j = i; j < NG * 2 * D; j += stride) g_enc[j] = 0.0f;
  for (int j = i; j < NG * D; j += stride){ g_poolmax[j] = 0.0f; g_poolsum[j] = 0.0f; }
  if (i < NG) g_cnt[i] = 0;
}

__global__ void count_kernel(const int* __restrict__ batch){
  int i = blockIdx.x * blockDim.x + threadIdx.x;
  if (i < NN) atomicAdd(&g_cnt[batch[i]], 1);
}

// ---------------- node projection: Ph[n] = [W blocks] @ h[n] (+bias), fp16 out ----
// Wsm row r (0..199): r<50 -> Af rows (Wf[r][0:50]) ; r<100 -> Bf rows (Wf[r-50][50:100])
//                     r<150 -> As rows (Ws[r-100][0:50]) ; else Bs rows (Ws[r-150][50:100])
__global__ void __launch_bounds__(256) proj_kernel(
    const float* __restrict__ x, int layer,
    const float* __restrict__ Wf, const float* __restrict__ Ws,
    const float* __restrict__ bf, const float* __restrict__ bs){
  __shared__ __align__(16) float Wsm[200][52];
  __shared__ float bsm[100];
  int t = threadIdx.x;
  for (int i = t; i < 200 * 52; i += blockDim.x){
    int r = i / 52, k = i - r * 52;
    float w = 0.0f;
    if (k < 50){
      if      (r <  50) w = Wf[ r        * DZ +      k];
      else if (r < 100) w = Wf[(r -  50) * DZ + 50 + k];
      else if (r < 150) w = Ws[(r - 100) * DZ +      k];
      else              w = Ws[(r - 150) * DZ + 50 + k];
    }
    Wsm[r][k] = w;
  }
  if (t < 50){ bsm[t] = bf[t]; bsm[50 + t] = bs[t]; }
  __syncthreads();

  int n = blockIdx.x * blockDim.x + t;
  if (n >= NN) return;

  const float* h = layer_in(x, layer);
  float hr[52];
  const float2* hp = reinterpret_cast<const float2*>(h + (size_t)n * D);
  #pragma unroll
  for (int i = 0; i < 25; i++){ float2 v = hp[i]; hr[2*i] = v.x; hr[2*i+1] = v.y; }
  hr[50] = 0.0f; hr[51] = 0.0f;

  __half* out = g_Ph + (size_t)n * 200;

  auto dot4 = [&](int r0, int r1, int r2, int r3,
                  float b0, float b1, float b2, float b3) -> uint2 {
    float a0 = b0, a1 = b1, a2 = b2, a3 = b3;
    #pragma unroll
    for (int k = 0; k < 52; k += 4){
      float4 w0 = *reinterpret_cast<const float4*>(&Wsm[r0][k]);
      float4 w1 = *reinterpret_cast<const float4*>(&Wsm[r1][k]);
      float4 w2 = *reinterpret_cast<const float4*>(&Wsm[r2][k]);
      float4 w3 = *reinterpret_cast<const float4*>(&Wsm[r3][k]);
      a0 += w0.x*hr[k] + w0.y*hr[k+1] + w0.z*hr[k+2] + w0.w*hr[k+3];
      a1 += w1.x*hr[k] + w1.y*hr[k+1] + w1.z*hr[k+2] + w1.w*hr[k+3];
      a2 += w2.x*hr[k] + w2.y*hr[k+1] + w2.z*hr[k+2] + w2.w*hr[k+3];
      a3 += w3.x*hr[k] + w3.y*hr[k+1] + w3.z*hr[k+2] + w3.w*hr[k+3];
    }
    __half2 p0 = __floats2half2_rn(a0, a1);
    __half2 p1 = __floats2half2_rn(a2, a3);
    return make_uint2(*reinterpret_cast<uint32_t*>(&p0), *reinterpret_cast<uint32_t*>(&p1));
  };

  #pragma unroll 1
  for (int p = 0; p < 25; p++){
    int c = 2 * p;
    // dst part: Af[c],Af[c+1] (rows c,c+1; bias bf) + As[c],As[c+1] (rows 100+c; bias bs)
    uint2 dpart = dot4(c, c + 1, 100 + c, 101 + c,
                       bsm[c], bsm[c + 1], bsm[50 + c], bsm[51 + c]);
    *reinterpret_cast<uint2*>(out + 4 * p) = dpart;
    // src part: Bf[c],Bf[c+1] (rows 50+c) + Bs[c],Bs[c+1] (rows 150+c), no bias
    uint2 spart = dot4(50 + c, 51 + c, 150 + c, 151 + c, 0.f, 0.f, 0.f, 0.f);
    *reinterpret_cast<uint2*>(out + 100 + 4 * p) = spart;
  }
}

// ---------------- edge kernel: gather-gate-scatter, edge-pair unrolled ----------------
// 250 active threads/block = 10 pair-lanes × 25 channel-pairs. Each thread handles
// edges (2g, 2g+1) per iteration: 1 int2 src + 1 int2 dst index load, 2×8B gathers
// per edge, 4 contiguous float4 ea loads, 2 independent gate/RED chains -> 2x MLP.
__global__ void __launch_bounds__(256, 4) edge_kernel(
    const int* __restrict__ ei, const float* __restrict__ ea,
    const float* __restrict__ Wf, const float* __restrict__ Ws){
  int t = threadIdx.x;
  if (t >= 250) return;
  int p  = t % 25;
  int c0 = 2 * p;

  float wf0[8], wf1[8], ws0[8], ws1[8];
  #pragma unroll
  for (int k = 0; k < 8; k++){
    wf0[k] = Wf[ c0      * DZ + 100 + k];
    wf1[k] = Wf[(c0 + 1) * DZ + 100 + k];
    ws0[k] = Ws[ c0      * DZ + 100 + k];
    ws1[k] = Ws[(c0 + 1) * DZ + 100 + k];
  }

  const __half* Pb = g_Ph;
  int base = blockIdx.x * 10 + t / 25;      // pair-lane in [0, 20000)
  #pragma unroll 1
  for (int j = 0; j < 40; j++){             // 20000 lanes * 40 iters * 2 edges = 1.6M
    int g  = base + j * 20000;              // pair index in [0, 800000)
    int e0 = 2 * g;
    int2 sidx = __ldg(reinterpret_cast<const int2*>(ei + e0));        // src(e0), src(e0+1)
    int2 didx = __ldg(reinterpret_cast<const int2*>(ei + NE + e0));   // dst(e0), dst(e0+1)

    const __half* PdA = Pb + (size_t)didx.x * 200;
    const __half* PsA = Pb + (size_t)sidx.x * 200;
    const __half* PdB = Pb + (size_t)didx.y * 200;
    const __half* PsB = Pb + (size_t)sidx.y * 200;
    uint2 dA = __ldg(reinterpret_cast<const uint2*>(PdA + 4 * p));
    uint2 sA = __ldg(reinterpret_cast<const uint2*>(PsA + 100 + 4 * p));
    uint2 dB = __ldg(reinterpret_cast<const uint2*>(PdB + 4 * p));
    uint2 sB = __ldg(reinterpret_cast<const uint2*>(PsB + 100 + 4 * p));

    const float4* eap = reinterpret_cast<const float4*>(ea + (size_t)e0 * 8);
    float4 eA0 = __ldg(eap);
    float4 eA1 = __ldg(eap + 1);
    float4 eB0 = __ldg(eap + 2);
    float4 eB1 = __ldg(eap + 3);

    // ---- edge A ----
    {
      float2 af  = __half22float2(u2h(dA.x));
      float2 as2 = __half22float2(u2h(dA.y));
      float2 bf2 = __half22float2(u2h(sA.x));
      float2 bs2 = __half22float2(u2h(sA.y));
      float f0 = af.x + bf2.x
               + wf0[0]*eA0.x + wf0[1]*eA0.y + wf0[2]*eA0.z + wf0[3]*eA0.w
               + wf0[4]*eA1.x + wf0[5]*eA1.y + wf0[6]*eA1.z + wf0[7]*eA1.w;
      float f1 = af.y + bf2.y
               + wf1[0]*eA0.x + wf1[1]*eA0.y + wf1[2]*eA0.z + wf1[3]*eA0.w
               + wf1[4]*eA1.x + wf1[5]*eA1.y + wf1[6]*eA1.z + wf1[7]*eA1.w;
      float g0 = as2.x + bs2.x
               + ws0[0]*eA0.x + ws0[1]*eA0.y + ws0[2]*eA0.z + ws0[3]*eA0.w
               + ws0[4]*eA1.x + ws0[5]*eA1.y + ws0[6]*eA1.z + ws0[7]*eA1.w;
      float g1 = as2.y + bs2.y
               + ws1[0]*eA0.x + ws1[1]*eA0.y + ws1[2]*eA0.z + ws1[3]*eA0.w
               + ws1[4]*eA1.x + ws1[5]*eA1.y + ws1[6]*eA1.z + ws1[7]*eA1.w;
      float2 m = make_float2(sigm(f0) * softp(g0), sigm(f1) * softp(g1));
      atomicAdd(reinterpret_cast<float2*>(g_msg + (size_t)didx.x * D + c0), m);
    }
    // ---- edge B ----
    {
      float2 af  = __half22float2(u2h(dB.x));
      float2 as2 = __half22float2(u2h(dB.y));
      float2 bf2 = __half22float2(u2h(sB.x));
      float2 bs2 = __half22float2(u2h(sB.y));
      float f0 = af.x + bf2.x
               + wf0[0]*eB0.x + wf0[1]*eB0.y + wf0[2]*eB0.z + wf0[3]*eB0.w
               + wf0[4]*eB1.x + wf0[5]*eB1.y + wf0[6]*eB1.z + wf0[7]*eB1.w;
      float f1 = af.y + bf2.y
               + wf1[0]*eB0.x + wf1[1]*eB0.y + wf1[2]*eB0.z + wf1[3]*eB0.w
               + wf1[4]*eB1.x + wf1[5]*eB1.y + wf1[6]*eB1.z + wf1[7]*eB1.w;
      float g0 = as2.x + bs2.x
               + ws0[0]*eB0.x + ws0[1]*eB0.y + ws0[2]*eB0.z + ws0[3]*eB0.w
               + ws0[4]*eB1.x + ws0[5]*eB1.y + ws0[6]*eB1.z + ws0[7]*eB1.w;
      float g1 = as2.y + bs2.y
               + ws1[0]*eB0.x + ws1[1]*eB0.y + ws1[2]*eB0.z + ws1[3]*eB0.w
               + ws1[4]*eB1.x + ws1[5]*eB1.y + ws1[6]*eB1.z + ws1[7]*eB1.w;
      float2 m = make_float2(sigm(f0) * softp(g0), sigm(f1) * softp(g1));
      atomicAdd(reinterpret_cast<float2*>(g_msg + (size_t)didx.y * D + c0), m);
    }
  }
}

// ---------------- finalize: residual + ReLU + smem-pooled max/sum ----------------
// batch is SORTED: a 10-node block usually spans 1-2 graphs. Pre-reduce into
// smem slots, flush once per (slot, channel). Also resets g_msg for next layer.
#define FN_NODES 10
#define FN_SLOTS 16
__global__ void __launch_bounds__(512) finalize_kernel(const float* __restrict__ x, int layer,
                                                       const int* __restrict__ batch){
  __shared__ float s_max[FN_SLOTS][50];
  __shared__ float s_sum[FN_SLOTS][50];
  __shared__ int s_bmin;
  __shared__ unsigned s_used;
  const float* h_in = layer_in(x, layer);
  float* h_out = layer_out(layer);
  int t = threadIdx.x;
  for (int i = t; i < FN_SLOTS * 50; i += 512){
    (&s_max[0][0])[i] = 0.0f; (&s_sum[0][0])[i] = 0.0f;
  }
  if (t == 0){
    int n0 = blockIdx.x * FN_NODES; if (n0 >= NN) n0 = NN - 1;
    s_bmin = batch[n0]; s_used = 0u;
  }
  __syncthreads();
  int bmin = s_bmin;

  if (t < FN_NODES * 50){
    int nl = t / 50, c = t - nl * 50;
    int n = blockIdx.x * FN_NODES + nl;
    if (n < NN){
      size_t i = (size_t)n * D + c;
      float v = fmaxf(g_msg[i] + h_in[i], 0.0f);
      h_out[i] = v;
      g_msg[i] = 0.0f;                       // reset for next layer / next launch
      int b = batch[n];
      int s = b - bmin;
      if ((unsigned)s < FN_SLOTS){
        atomicMax(reinterpret_cast<int*>(&s_max[s][c]), __float_as_int(v));
        atomicAdd(&s_sum[s][c], v);
        if (c == 0) atomicOr(&s_used, 1u << s);
      } else {
        atomicMax(reinterpret_cast<int*>(&g_poolmax[b * D + c]), __float_as_int(v));
        atomicAdd(&g_poolsum[b * D + c], v);
      }
    }
  }
  __syncthreads();
  unsigned used = s_used;
  for (int i = t; i < FN_SLOTS * 50; i += 512){
    int s = i / 50, c = i - s * 50;
    if (used & (1u << s)){
      int b = bmin + s;
      float mv = s_max[s][c];
      if (mv > 0.0f) atomicMax(reinterpret_cast<int*>(&g_poolmax[b * D + c]), __float_as_int(mv));
      float sv = s_sum[s][c];
      if (sv != 0.0f) atomicAdd(&g_poolsum[b * D + c], sv);
    }
  }
}

// accumulate pooled features into enc, re-zero pool buffers for next layer
__global__ void acc_enc_kernel(){
  int i = blockIdx.x * blockDim.x + threadIdx.x;
  if (i >= NG * D) return;
  int b = i / D, c = i - b * D;
  g_enc[b * 100 + c]      += g_poolmax[i];
  g_enc[b * 100 + 50 + c] += g_poolsum[i] / fmaxf((float)g_cnt[b], 1.0f);
  g_poolmax[i] = 0.0f;
  g_poolsum[i] = 0.0f;
}

// ---------------- head: linear + log_softmax; emit [logp | enc] ----------------
__global__ void head_kernel(const float* __restrict__ lw, const float* __restrict__ lb,
                            float* __restrict__ out, int out_size){
  int b = blockIdx.x * blockDim.x + threadIdx.x;
  if (b >= NG) return;
  float e[100];
  #pragma unroll
  for (int k = 0; k < 100; k++) e[k] = g_enc[b * 100 + k];
  float lg[NOUT];
  #pragma unroll
  for (int j = 0; j < NOUT; j++){
    float acc = lb[j];
    #pragma unroll
    for (int k = 0; k < 100; k++) acc += e[k] * lw[j * 100 + k];
    lg[j] = acc;
  }
  float mx = lg[0];
  #pragma unroll
  for (int j = 1; j < NOUT; j++) mx = fmaxf(mx, lg[j]);
  float ss = 0.0f;
  #pragma unroll
  for (int j = 0; j < NOUT; j++) ss += fast_ex2((lg[j] - mx) * kL2E);
  float lse = mx + kLN2 * fast_lg2(ss);
  #pragma unroll
  for (int j = 0; j < NOUT; j++) out[b * NOUT + j] = lg[j] - lse;
  if (out_size >= NG * NOUT + NG * 100){
    #pragma unroll 4
    for (int k = 0; k < 100; k++) out[NG * NOUT + b * 100 + k] = e[k];
  }
}

// ---------------- launch (pure kernel launches; graph-capture safe) ----------------
extern "C" void kernel_launch(void* const* d_in, const int* in_sizes, int n_in,
                              void* d_out, int out_size){
  (void)in_sizes; (void)n_in;
  const float* x  = (const float*)d_in[0];
  const int*   ei = (const int*)  d_in[1];
  const float* ea = (const float*)d_in[2];
  const int*   bt = (const int*)  d_in[3];
  const float* Wf = (const float*)d_in[4];
  const float* bf = (const float*)d_in[5];
  const float* Ws = (const float*)d_in[6];
  const float* bs = (const float*)d_in[7];
  const float* lw = (const float*)d_in[8];
  const float* lb = (const float*)d_in[9];
  float* out = (float*)d_out;

  zero_global_bufs<<<128, 256>>>();
  count_kernel<<<(NN + 255) / 256, 256>>>(bt);

  for (int i = 0; i < 3; i++){
    proj_kernel<<<(NN + 255) / 256, 256>>>(x, i, Wf + i * D * DZ, Ws + i * D * DZ,
                                           bf + i * D, bs + i * D);
    edge_kernel<<<2000, 256>>>(ei, ea, Wf + i * D * DZ, Ws + i * D * DZ);
    finalize_kernel<<<(NN + FN_NODES - 1) / FN_NODES, 512>>>(x, i, bt);
    acc_enc_kernel<<<(NG * D + 255) / 256, 256>>>();
  }

  head_kernel<<<(NG + 127) / 128, 128>>>(lw, lb, out, out_size);
}

// round 7
// speedup vs baseline: 1.9644x; 1.1869x over previous
#include <cuda_runtime.h>
#include <cuda_fp16.h>
#include <cstdint>

#define NN 100000
#define NE 1600000
#define NG 512
#define D  50
#define DE 8
#define DZ 108
#define NOUT 10

// ---------------- device scratch (no runtime allocation allowed) ----------------
// Projection table Ph[n][200] (fp16), interleaved per channel-pair p (p=0..24):
//   halves [4p .. 4p+3]         = Af[2p], Af[2p+1], As[2p], As[2p+1]  (dst part, biases folded)
//   halves [100+4p .. 100+4p+3] = Bf[2p], Bf[2p+1], Bs[2p], Bs[2p+1]  (src part)
__device__ __align__(16) __half g_Ph[(size_t)NN * 200];
__device__ __align__(16) __half g_eah[(size_t)NE * 8];  // fp16 edge_attr (layer-invariant)
__device__ __align__(16) float g_msg[(size_t)NN * D];   // scatter accumulator (kept zeroed)
__device__ __align__(16) float g_h0[(size_t)NN * D];    // ping-pong h buffers
__device__ __align__(16) float g_h1[(size_t)NN * D];
__device__ float g_poolmax[NG * D];
__device__ float g_poolsum[NG * D];
__device__ int   g_cnt[NG];
__device__ float g_enc[NG * 2 * D];

constexpr float kL2E = 1.4426950408889634f;   // log2(e)
constexpr float kLN2 = 0.6931471805599453f;   // ln(2)

__device__ __forceinline__ float fast_ex2(float x){ float y; asm("ex2.approx.ftz.f32 %0, %1;" : "=f"(y) : "f"(x)); return y; }
__device__ __forceinline__ float fast_lg2(float x){ float y; asm("lg2.approx.ftz.f32 %0, %1;" : "=f"(y) : "f"(x)); return y; }
__device__ __forceinline__ float fast_rcp(float x){ float y; asm("rcp.approx.ftz.f32 %0, %1;" : "=f"(y) : "f"(x)); return y; }

__device__ __forceinline__ float sigm(float x){
  return fast_rcp(1.0f + fast_ex2(-x * kL2E));
}
__device__ __forceinline__ float softp(float x){
  float t = fast_ex2(-fabsf(x) * kL2E);
  return fmaxf(x, 0.0f) + kLN2 * fast_lg2(1.0f + t);
}

__device__ __forceinline__ __half2 u2h(uint32_t u){ return *reinterpret_cast<__half2*>(&u); }

// In-device ping-pong selection (layer: 0 -> x->h0, 1 -> h0->h1, 2 -> h1->h0)
__device__ __forceinline__ const float* layer_in(const float* x, int layer){
  if (layer == 0) return x;
  if (layer == 1) return g_h0;
  return g_h1;
}
__device__ __forceinline__ float* layer_out(int layer){
  return (layer == 1) ? g_h1 : g_h0;
}

// ---------------- setup ----------------
__global__ void zero_global_bufs(){
  int i = blockIdx.x * blockDim.x + threadIdx.x;
  int stride = gridDim.x * blockDim.x;
  for (int j = i; j < NG * 2 * D; j += stride) g_enc[j] = 0.0f;
  for (int j = i; j < NG * D; j += stride){ g_poolmax[j] = 0.0f; g_poolsum[j] = 0.0f; }
  if (i < NG) g_cnt[i] = 0;
}

__global__ void count_kernel(const int* __restrict__ batch){
  int i = blockIdx.x * blockDim.x + threadIdx.x;
  if (i < NN) atomicAdd(&g_cnt[batch[i]], 1);
}

// convert edge_attr to fp16 once per launch (2 edges / thread, grid-stride)
__global__ void ea_half_kernel(const float* __restrict__ ea){
  int stride = gridDim.x * blockDim.x;
  for (int i = blockIdx.x * blockDim.x + threadIdx.x; i < NE / 2; i += stride){
    const float4* src = reinterpret_cast<const float4*>(ea + (size_t)i * 16);
    float4 a = __ldg(src), b = __ldg(src + 1), c = __ldg(src + 2), d = __ldg(src + 3);
    __half2 h0 = __floats2half2_rn(a.x, a.y), h1 = __floats2half2_rn(a.z, a.w);
    __half2 h2 = __floats2half2_rn(b.x, b.y), h3 = __floats2half2_rn(b.z, b.w);
    __half2 h4 = __floats2half2_rn(c.x, c.y), h5 = __floats2half2_rn(c.z, c.w);
    __half2 h6 = __floats2half2_rn(d.x, d.y), h7 = __floats2half2_rn(d.z, d.w);
    uint4* dst = reinterpret_cast<uint4*>(g_eah + (size_t)i * 16);
    dst[0] = make_uint4(*reinterpret_cast<uint32_t*>(&h0), *reinterpret_cast<uint32_t*>(&h1),
                        *reinterpret_cast<uint32_t*>(&h2), *reinterpret_cast<uint32_t*>(&h3));
    dst[1] = make_uint4(*reinterpret_cast<uint32_t*>(&h4), *reinterpret_cast<uint32_t*>(&h5),
                        *reinterpret_cast<uint32_t*>(&h6), *reinterpret_cast<uint32_t*>(&h7));
  }
}

// ---------------- node projection: Ph[n] = [W blocks] @ h[n] (+bias), fp16 out ----
__global__ void __launch_bounds__(256) proj_kernel(
    const float* __restrict__ x, int layer,
    const float* __restrict__ Wf, const float* __restrict__ Ws,
    const float* __restrict__ bf, const float* __restrict__ bs){
  __shared__ __align__(16) float Wsm[200][52];
  __shared__ float bsm[100];
  int t = threadIdx.x;
  for (int i = t; i < 200 * 52; i += blockDim.x){
    int r = i / 52, k = i - r * 52;
    float w = 0.0f;
    if (k < 50){
      if      (r <  50) w = Wf[ r        * DZ +      k];
      else if (r < 100) w = Wf[(r -  50) * DZ + 50 + k];
      else if (r < 150) w = Ws[(r - 100) * DZ +      k];
      else              w = Ws[(r - 150) * DZ + 50 + k];
    }
    Wsm[r][k] = w;
  }
  if (t < 50){ bsm[t] = bf[t]; bsm[50 + t] = bs[t]; }
  __syncthreads();

  int n = blockIdx.x * blockDim.x + t;
  if (n >= NN) return;

  const float* h = layer_in(x, layer);
  float hr[52];
  const float2* hp = reinterpret_cast<const float2*>(h + (size_t)n * D);
  #pragma unroll
  for (int i = 0; i < 25; i++){ float2 v = hp[i]; hr[2*i] = v.x; hr[2*i+1] = v.y; }
  hr[50] = 0.0f; hr[51] = 0.0f;

  __half* out = g_Ph + (size_t)n * 200;

  auto dot4 = [&](int r0, int r1, int r2, int r3,
                  float b0, float b1, float b2, float b3) -> uint2 {
    float a0 = b0, a1 = b1, a2 = b2, a3 = b3;
    #pragma unroll
    for (int k = 0; k < 52; k += 4){
      float4 w0 = *reinterpret_cast<const float4*>(&Wsm[r0][k]);
      float4 w1 = *reinterpret_cast<const float4*>(&Wsm[r1][k]);
      float4 w2 = *reinterpret_cast<const float4*>(&Wsm[r2][k]);
      float4 w3 = *reinterpret_cast<const float4*>(&Wsm[r3][k]);
      a0 += w0.x*hr[k] + w0.y*hr[k+1] + w0.z*hr[k+2] + w0.w*hr[k+3];
      a1 += w1.x*hr[k] + w1.y*hr[k+1] + w1.z*hr[k+2] + w1.w*hr[k+3];
      a2 += w2.x*hr[k] + w2.y*hr[k+1] + w2.z*hr[k+2] + w2.w*hr[k+3];
      a3 += w3.x*hr[k] + w3.y*hr[k+1] + w3.z*hr[k+2] + w3.w*hr[k+3];
    }
    __half2 p0 = __floats2half2_rn(a0, a1);
    __half2 p1 = __floats2half2_rn(a2, a3);
    return make_uint2(*reinterpret_cast<uint32_t*>(&p0), *reinterpret_cast<uint32_t*>(&p1));
  };

  #pragma unroll 1
  for (int p = 0; p < 25; p++){
    int c = 2 * p;
    uint2 dpart = dot4(c, c + 1, 100 + c, 101 + c,
                       bsm[c], bsm[c + 1], bsm[50 + c], bsm[51 + c]);
    *reinterpret_cast<uint2*>(out + 4 * p) = dpart;
    uint2 spart = dot4(50 + c, 51 + c, 150 + c, 151 + c, 0.f, 0.f, 0.f, 0.f);
    *reinterpret_cast<uint2*>(out + 100 + 4 * p) = spart;
  }
}

// ---------------- edge kernel: gather-gate-scatter, 4-edge unrolled, HFMA2 ----------
// 250 active threads/block = 10 quad-lanes × 25 channel-pairs. Each thread handles
// 4 consecutive edges per iteration: int4 index loads, 8 independent 8B gathers,
// uint4 fp16 ea loads, half2 gate pre-activation math, float2 RED scatter.
__global__ void __launch_bounds__(256, 3) edge_kernel(
    const int* __restrict__ ei,
    const float* __restrict__ Wf, const float* __restrict__ Ws){
  int t = threadIdx.x;
  if (t >= 250) return;
  int p  = t % 25;
  int c0 = 2 * p;

  // packed half2 weights: whf[k] = (Wf[c0][100+k], Wf[c0+1][100+k]); whs likewise
  __half2 whf[8], whs[8];
  #pragma unroll
  for (int k = 0; k < 8; k++){
    whf[k] = __floats2half2_rn(Wf[c0 * DZ + 100 + k], Wf[(c0 + 1) * DZ + 100 + k]);
    whs[k] = __floats2half2_rn(Ws[c0 * DZ + 100 + k], Ws[(c0 + 1) * DZ + 100 + k]);
  }

  const __half* Pb = g_Ph;
  int base = blockIdx.x * 10 + t / 25;        // quad-lane in [0, 20000)

  #pragma unroll 1
  for (int j = 0; j < 20; j++){               // 20000 lanes * 20 iters * 4 edges = 1.6M
    int g  = base + j * 20000;                // quad index in [0, 400000)
    int e0 = 4 * g;
    int4 sidx = __ldg(reinterpret_cast<const int4*>(ei + e0));        // src of 4 edges
    int4 didx = __ldg(reinterpret_cast<const int4*>(ei + NE + e0));   // dst of 4 edges

    uint2 dG[4], sG[4];
    dG[0] = __ldg(reinterpret_cast<const uint2*>(Pb + (size_t)didx.x * 200 + 4 * p));
    dG[1] = __ldg(reinterpret_cast<const uint2*>(Pb + (size_t)didx.y * 200 + 4 * p));
    dG[2] = __ldg(reinterpret_cast<const uint2*>(Pb + (size_t)didx.z * 200 + 4 * p));
    dG[3] = __ldg(reinterpret_cast<const uint2*>(Pb + (size_t)didx.w * 200 + 4 * p));
    sG[0] = __ldg(reinterpret_cast<const uint2*>(Pb + (size_t)sidx.x * 200 + 100 + 4 * p));
    sG[1] = __ldg(reinterpret_cast<const uint2*>(Pb + (size_t)sidx.y * 200 + 100 + 4 * p));
    sG[2] = __ldg(reinterpret_cast<const uint2*>(Pb + (size_t)sidx.z * 200 + 100 + 4 * p));
    sG[3] = __ldg(reinterpret_cast<const uint2*>(Pb + (size_t)sidx.w * 200 + 100 + 4 * p));

    uint4 eaq[4];
    const uint4* eap = reinterpret_cast<const uint4*>(g_eah + (size_t)e0 * 8);
    eaq[0] = __ldg(eap + 0);
    eaq[1] = __ldg(eap + 1);
    eaq[2] = __ldg(eap + 2);
    eaq[3] = __ldg(eap + 3);

    int dsts[4] = {didx.x, didx.y, didx.z, didx.w};
    #pragma unroll
    for (int q = 0; q < 4; q++){
      __half2 ea01 = u2h(eaq[q].x), ea23 = u2h(eaq[q].y);
      __half2 ea45 = u2h(eaq[q].z), ea67 = u2h(eaq[q].w);
      __half2 f2 = __hadd2(u2h(dG[q].x), u2h(sG[q].x));   // Af+Bf (bias folded in Af)
      __half2 s2 = __hadd2(u2h(dG[q].y), u2h(sG[q].y));   // As+Bs
      f2 = __hfma2(whf[0], __low2half2(ea01),  f2);  s2 = __hfma2(whs[0], __low2half2(ea01),  s2);
      f2 = __hfma2(whf[1], __high2half2(ea01), f2);  s2 = __hfma2(whs[1], __high2half2(ea01), s2);
      f2 = __hfma2(whf[2], __low2half2(ea23),  f2);  s2 = __hfma2(whs[2], __low2half2(ea23),  s2);
      f2 = __hfma2(whf[3], __high2half2(ea23), f2);  s2 = __hfma2(whs[3], __high2half2(ea23), s2);
      f2 = __hfma2(whf[4], __low2half2(ea45),  f2);  s2 = __hfma2(whs[4], __low2half2(ea45),  s2);
      f2 = __hfma2(whf[5], __high2half2(ea45), f2);  s2 = __hfma2(whs[5], __high2half2(ea45), s2);
      f2 = __hfma2(whf[6], __low2half2(ea67),  f2);  s2 = __hfma2(whs[6], __low2half2(ea67),  s2);
      f2 = __hfma2(whf[7], __high2half2(ea67), f2);  s2 = __hfma2(whs[7], __high2half2(ea67), s2);
      float2 f = __half22float2(f2);
      float2 s = __half22float2(s2);
      float2 m = make_float2(sigm(f.x) * softp(s.x), sigm(f.y) * softp(s.y));
      atomicAdd(reinterpret_cast<float2*>(g_msg + (size_t)dsts[q] * D + c0), m);
    }
  }
}

// ---------------- finalize: residual + ReLU + smem-pooled max/sum ----------------
#define FN_NODES 10
#define FN_SLOTS 16
__global__ void __launch_bounds__(512) finalize_kernel(const float* __restrict__ x, int layer,
                                                       const int* __restrict__ batch){
  __shared__ float s_max[FN_SLOTS][50];
  __shared__ float s_sum[FN_SLOTS][50];
  __shared__ int s_bmin;
  __shared__ unsigned s_used;
  const float* h_in = layer_in(x, layer);
  float* h_out = layer_out(layer);
  int t = threadIdx.x;
  for (int i = t; i < FN_SLOTS * 50; i += 512){
    (&s_max[0][0])[i] = 0.0f; (&s_sum[0][0])[i] = 0.0f;
  }
  if (t == 0){
    int n0 = blockIdx.x * FN_NODES; if (n0 >= NN) n0 = NN - 1;
    s_bmin = batch[n0]; s_used = 0u;
  }
  __syncthreads();
  int bmin = s_bmin;

  if (t < FN_NODES * 50){
    int nl = t / 50, c = t - nl * 50;
    int n = blockIdx.x * FN_NODES + nl;
    if (n < NN){
      size_t i = (size_t)n * D + c;
      float v = fmaxf(g_msg[i] + h_in[i], 0.0f);
      h_out[i] = v;
      g_msg[i] = 0.0f;                       // reset for next layer / next launch
      int b = batch[n];
      int s = b - bmin;
      if ((unsigned)s < FN_SLOTS){
        atomicMax(reinterpret_cast<int*>(&s_max[s][c]), __float_as_int(v));
        atomicAdd(&s_sum[s][c], v);
        if (c == 0) atomicOr(&s_used, 1u << s);
      } else {
        atomicMax(reinterpret_cast<int*>(&g_poolmax[b * D + c]), __float_as_int(v));
        atomicAdd(&g_poolsum[b * D + c], v);
      }
    }
  }
  __syncthreads();
  unsigned used = s_used;
  for (int i = t; i < FN_SLOTS * 50; i += 512){
    int s = i / 50, c = i - s * 50;
    if (used & (1u << s)){
      int b = bmin + s;
      float mv = s_max[s][c];
      if (mv > 0.0f) atomicMax(reinterpret_cast<int*>(&g_poolmax[b * D + c]), __float_as_int(mv));
      float sv = s_sum[s][c];
      if (sv != 0.0f) atomicAdd(&g_poolsum[b * D + c], sv);
    }
  }
}

// accumulate pooled features into enc, re-zero pool buffers for next layer
__global__ void acc_enc_kernel(){
  int i = blockIdx.x * blockDim.x + threadIdx.x;
  if (i >= NG * D) return;
  int b = i / D, c = i - b * D;
  g_enc[b * 100 + c]      += g_poolmax[i];
  g_enc[b * 100 + 50 + c] += g_poolsum[i] / fmaxf((float)g_cnt[b], 1.0f);
  g_poolmax[i] = 0.0f;
  g_poolsum[i] = 0.0f;
}

// ---------------- head: linear + log_softmax; emit [logp | enc] ----------------
__global__ void head_kernel(const float* __restrict__ lw, const float* __restrict__ lb,
                            float* __restrict__ out, int out_size){
  int b = blockIdx.x * blockDim.x + threadIdx.x;
  if (b >= NG) return;
  float e[100];
  #pragma unroll
  for (int k = 0; k < 100; k++) e[k] = g_enc[b * 100 + k];
  float lg[NOUT];
  #pragma unroll
  for (int j = 0; j < NOUT; j++){
    float acc = lb[j];
    #pragma unroll
    for (int k = 0; k < 100; k++) acc += e[k] * lw[j * 100 + k];
    lg[j] = acc;
  }
  float mx = lg[0];
  #pragma unroll
  for (int j = 1; j < NOUT; j++) mx = fmaxf(mx, lg[j]);
  float ss = 0.0f;
  #pragma unroll
  for (int j = 0; j < NOUT; j++) ss += fast_ex2((lg[j] - mx) * kL2E);
  float lse = mx + kLN2 * fast_lg2(ss);
  #pragma unroll
  for (int j = 0; j < NOUT; j++) out[b * NOUT + j] = lg[j] - lse;
  if (out_size >= NG * NOUT + NG * 100){
    #pragma unroll 4
    for (int k = 0; k < 100; k++) out[NG * NOUT + b * 100 + k] = e[k];
  }
}

// ---------------- launch (pure kernel launches; graph-capture safe) ----------------
extern "C" void kernel_launch(void* const* d_in, const int* in_sizes, int n_in,
                              void* d_out, int out_size){
  (void)in_sizes; (void)n_in;
  const float* x  = (const float*)d_in[0];
  const int*   ei = (const int*)  d_in[1];
  const float* ea = (const float*)d_in[2];
  const int*   bt = (const int*)  d_in[3];
  const float* Wf = (const float*)d_in[4];
  const float* bf = (const float*)d_in[5];
  const float* Ws = (const float*)d_in[6];
  const float* bs = (const float*)d_in[7];
  const float* lw = (const float*)d_in[8];
  const float* lb = (const float*)d_in[9];
  float* out = (float*)d_out;

  zero_global_bufs<<<128, 256>>>();
  count_kernel<<<(NN + 255) / 256, 256>>>(bt);
  ea_half_kernel<<<1024, 256>>>(ea);

  for (int i = 0; i < 3; i++){
    proj_kernel<<<(NN + 255) / 256, 256>>>(x, i, Wf + i * D * DZ, Ws + i * D * DZ,
                                           bf + i * D, bs + i * D);
    edge_kernel<<<2000, 256>>>(ei, Wf + i * D * DZ, Ws + i * D * DZ);
    finalize_kernel<<<(NN + FN_NODES - 1) / FN_NODES, 512>>>(x, i, bt);
    acc_enc_kernel<<<(NG * D + 255) / 256, 256>>>();
  }

  head_kernel<<<(NG + 127) / 128, 128>>>(lw, lb, out, out_size);
}

// round 8
// speedup vs baseline: 2.4621x; 1.2534x over previous
#include <cuda_runtime.h>
#include <cuda_fp16.h>
#include <cstdint>

#define NN 100000
#define NE 1600000
#define NG 512
#define D  50
#define DE 8
#define DZ 108
#define NOUT 10

// ---------------- device scratch (no runtime allocation allowed) ----------------
// Projection table Ph[n][200] (fp16), interleaved per channel-pair p (p=0..24):
//   halves [4p .. 4p+3]         = Af[2p], Af[2p+1], As[2p], As[2p+1]  (dst part, biases folded)
//   halves [100+4p .. 100+4p+3] = Bf[2p], Bf[2p+1], Bs[2p], Bs[2p+1]  (src part)
__device__ __align__(16) __half g_Ph[(size_t)NN * 200];
__device__ __align__(16) __half g_eah[(size_t)NE * 8];  // fp16 edge_attr (layer-invariant)
__device__ __align__(16) float g_msg[(size_t)NN * D];   // scatter accumulator (kept zeroed)
__device__ __align__(16) float g_h0[(size_t)NN * D];    // ping-pong h buffers
__device__ __align__(16) float g_h1[(size_t)NN * D];
__device__ __align__(16) float g_Bt[200 * 60];          // tf32 weight matrix, Bt[n][k], layer-baked
__device__ float g_poolmax[NG * D];
__device__ float g_poolsum[NG * D];
__device__ int   g_cnt[NG];
__device__ float g_enc[NG * 2 * D];

constexpr float kL2E = 1.4426950408889634f;   // log2(e)
constexpr float kLN2 = 0.6931471805599453f;   // ln(2)

__device__ __forceinline__ float fast_ex2(float x){ float y; asm("ex2.approx.ftz.f32 %0, %1;" : "=f"(y) : "f"(x)); return y; }
__device__ __forceinline__ float fast_lg2(float x){ float y; asm("lg2.approx.ftz.f32 %0, %1;" : "=f"(y) : "f"(x)); return y; }
__device__ __forceinline__ float fast_rcp(float x){ float y; asm("rcp.approx.ftz.f32 %0, %1;" : "=f"(y) : "f"(x)); return y; }

__device__ __forceinline__ float sigm(float x){
  return fast_rcp(1.0f + fast_ex2(-x * kL2E));
}
__device__ __forceinline__ float softp(float x){
  float t = fast_ex2(-fabsf(x) * kL2E);
  return fmaxf(x, 0.0f) + kLN2 * fast_lg2(1.0f + t);
}

__device__ __forceinline__ __half2 u2h(uint32_t u){ return *reinterpret_cast<__half2*>(&u); }
__device__ __forceinline__ uint32_t f2tf32(float v){
  uint32_t r; asm("cvt.rna.tf32.f32 %0, %1;" : "=r"(r) : "f"(v)); return r;
}

// In-device ping-pong selection (layer: 0 -> x->h0, 1 -> h0->h1, 2 -> h1->h0)
__device__ __forceinline__ const float* layer_in(const float* x, int layer){
  if (layer == 0) return x;
  if (layer == 1) return g_h0;
  return g_h1;
}
__device__ __forceinline__ float* layer_out(int layer){
  return (layer == 1) ? g_h1 : g_h0;
}

// ---------------- setup ----------------
__global__ void zero_global_bufs(){
  int i = blockIdx.x * blockDim.x + threadIdx.x;
  int stride = gridDim.x * blockDim.x;
  for (int j = i; j < NG * 2 * D; j += stride) g_enc[j] = 0.0f;
  for (int j = i; j < NG * D; j += stride){ g_poolmax[j] = 0.0f; g_poolsum[j] = 0.0f; }
  if (i < NG) g_cnt[i] = 0;
}

__global__ void count_kernel(const int* __restrict__ batch){
  int i = blockIdx.x * blockDim.x + threadIdx.x;
  if (i < NN) atomicAdd(&g_cnt[batch[i]], 1);
}

// convert edge_attr to fp16 once per launch (2 edges / thread, grid-stride)
__global__ void ea_half_kernel(const float* __restrict__ ea){
  int stride = gridDim.x * blockDim.x;
  for (int i = blockIdx.x * blockDim.x + threadIdx.x; i < NE / 2; i += stride){
    const float4* src = reinterpret_cast<const float4*>(ea + (size_t)i * 16);
    float4 a = __ldg(src), b = __ldg(src + 1), c = __ldg(src + 2), d = __ldg(src + 3);
    __half2 h0 = __floats2half2_rn(a.x, a.y), h1 = __floats2half2_rn(a.z, a.w);
    __half2 h2 = __floats2half2_rn(b.x, b.y), h3 = __floats2half2_rn(b.z, b.w);
    __half2 h4 = __floats2half2_rn(c.x, c.y), h5 = __floats2half2_rn(c.z, c.w);
    __half2 h6 = __floats2half2_rn(d.x, d.y), h7 = __floats2half2_rn(d.z, d.w);
    uint4* dst = reinterpret_cast<uint4*>(g_eah + (size_t)i * 16);
    dst[0] = make_uint4(*reinterpret_cast<uint32_t*>(&h0), *reinterpret_cast<uint32_t*>(&h1),
                        *reinterpret_cast<uint32_t*>(&h2), *reinterpret_cast<uint32_t*>(&h3));
    dst[1] = make_uint4(*reinterpret_cast<uint32_t*>(&h4), *reinterpret_cast<uint32_t*>(&h5),
                        *reinterpret_cast<uint32_t*>(&h6), *reinterpret_cast<uint32_t*>(&h7));
  }
}

// ---------------- per-layer weight bake: g_Bt[n][k] (tf32), output-interleaved ----
// n in [0,100): dst part, k cols [0:50); n in [100,200): src part, k cols [50:100)
// n%4: 0 -> Wf[2p], 1 -> Wf[2p+1], 2 -> Ws[2p], 3 -> Ws[2p+1]   (p = (n%100)/4)
__global__ void prep_B_kernel(const float* __restrict__ Wf, const float* __restrict__ Ws){
  int i = blockIdx.x * blockDim.x + threadIdx.x;
  if (i >= 200 * 60) return;
  int n = i / 60, k = i - n * 60;
  float v = 0.0f;
  if (k < 50){
    int p = (n % 100) >> 2, j = n & 3;
    int c = 2 * p + (j & 1);
    const float* W = (j < 2) ? Wf : Ws;
    int koff = (n < 100) ? k : (50 + k);
    v = W[c * DZ + koff];
  }
  reinterpret_cast<uint32_t*>(g_Bt)[i] = f2tf32(v);
}

// ---------------- node projection via tf32 mma.sync ----------------
// Block: 256 threads (8 warps), tile M=128 nodes x N=200 outputs x K=56 (52 padded).
// smem: sA[128][60] (tf32 h rows), sBt[200][60], sBias[200].  79.5 KB dynamic.
// Warp w computes rows 16w..16w+15 via m16n8k4 tf32 mma: 25 n-tiles x 14 k-steps.
#define PM_M 128
#define PM_SMEM_BYTES ((128 * 60 + 200 * 60 + 200) * 4)

__global__ void __launch_bounds__(256) proj_mma_kernel(
    const float* __restrict__ x, int layer,
    const float* __restrict__ bf, const float* __restrict__ bs){
  extern __shared__ float sm[];
  float* sA    = sm;                    // [128][60]
  float* sBt   = sm + 128 * 60;         // [200][60]
  float* sBias = sBt + 200 * 60;        // [200]
  int t = threadIdx.x;
  const float* h = layer_in(x, layer);
  int n0 = blockIdx.x * PM_M;

  // stage A (tf32-converted h rows, zero-padded)
  for (int i = t; i < 128 * 60; i += 256){
    int r = i / 60, k = i - r * 60;
    int node = n0 + r;
    float v = 0.0f;
    if (k < 50 && node < NN) v = h[(size_t)node * D + k];
    reinterpret_cast<uint32_t*>(sA)[i] = f2tf32(v);
  }
  // stage Bt (pre-baked) and bias
  {
    const float4* gB4 = reinterpret_cast<const float4*>(g_Bt);
    float4* sB4 = reinterpret_cast<float4*>(sBt);
    for (int i = t; i < 200 * 60 / 4; i += 256) sB4[i] = gB4[i];
    for (int i = t; i < 200; i += 256){
      float b = 0.0f;
      if (i < 100){
        int c = 2 * (i >> 2) + (i & 1);
        b = (i & 2) ? bs[c] : bf[c];
      }
      sBias[i] = b;
    }
  }
  __syncthreads();

  int w = t >> 5, lane = t & 31, g = lane >> 2, tg = lane & 3;
  const uint32_t* A = reinterpret_cast<const uint32_t*>(sA);
  const uint32_t* B = reinterpret_cast<const uint32_t*>(sBt);
  int r0 = w * 16 + g;

  // A fragments for all 14 k-steps (a0: row r0, a1: row r0+8; col = 4ks+tg)
  uint32_t a[14][2];
  #pragma unroll
  for (int ks = 0; ks < 14; ks++){
    int col = 4 * ks + tg;
    a[ks][0] = A[r0 * 60 + col];
    a[ks][1] = A[(r0 + 8) * 60 + col];
  }

  int node0 = n0 + r0;
  int node1 = node0 + 8;

  #pragma unroll 1
  for (int nt = 0; nt < 25; nt++){
    float c0 = 0.f, c1 = 0.f, c2 = 0.f, c3 = 0.f;
    int nb = nt * 8;
    #pragma unroll
    for (int ks = 0; ks < 14; ks++){
      uint32_t b = B[(nb + g) * 60 + 4 * ks + tg];   // Bt[n=nb+g][k=4ks+tg]
      asm volatile(
        "mma.sync.aligned.m16n8k4.row.col.f32.tf32.tf32.f32 "
        "{%0,%1,%2,%3}, {%4,%5}, {%6}, {%0,%1,%2,%3};"
        : "+f"(c0), "+f"(c1), "+f"(c2), "+f"(c3)
        : "r"(a[ks][0]), "r"(a[ks][1]), "r"(b));
    }
    int col0 = nb + 2 * tg;                          // even -> 8B-aligned bias, 4B-aligned store
    float2 bias = *reinterpret_cast<const float2*>(&sBias[col0]);
    if (node0 < NN){
      __half2 hv = __floats2half2_rn(c0 + bias.x, c1 + bias.y);
      *reinterpret_cast<uint32_t*>(g_Ph + (size_t)node0 * 200 + col0) =
          *reinterpret_cast<uint32_t*>(&hv);
    }
    if (node1 < NN){
      __half2 hv = __floats2half2_rn(c2 + bias.x, c3 + bias.y);
      *reinterpret_cast<uint32_t*>(g_Ph + (size_t)node1 * 200 + col0) =
          *reinterpret_cast<uint32_t*>(&hv);
    }
  }
}

// ---------------- edge kernel: gather-gate-scatter, 4-edge unrolled, HFMA2 ----------
__global__ void __launch_bounds__(256, 3) edge_kernel(
    const int* __restrict__ ei,
    const float* __restrict__ Wf, const float* __restrict__ Ws){
  int t = threadIdx.x;
  if (t >= 250) return;
  int p  = t % 25;
  int c0 = 2 * p;

  __half2 whf[8], whs[8];
  #pragma unroll
  for (int k = 0; k < 8; k++){
    whf[k] = __floats2half2_rn(Wf[c0 * DZ + 100 + k], Wf[(c0 + 1) * DZ + 100 + k]);
    whs[k] = __floats2half2_rn(Ws[c0 * DZ + 100 + k], Ws[(c0 + 1) * DZ + 100 + k]);
  }

  const __half* Pb = g_Ph;
  int base = blockIdx.x * 10 + t / 25;        // quad-lane in [0, 20000)

  #pragma unroll 1
  for (int j = 0; j < 20; j++){               // 20000 lanes * 20 iters * 4 edges = 1.6M
    int g  = base + j * 20000;
    int e0 = 4 * g;
    int4 sidx = __ldg(reinterpret_cast<const int4*>(ei + e0));
    int4 didx = __ldg(reinterpret_cast<const int4*>(ei + NE + e0));

    uint2 dG[4], sG[4];
    dG[0] = __ldg(reinterpret_cast<const uint2*>(Pb + (size_t)didx.x * 200 + 4 * p));
    dG[1] = __ldg(reinterpret_cast<const uint2*>(Pb + (size_t)didx.y * 200 + 4 * p));
    dG[2] = __ldg(reinterpret_cast<const uint2*>(Pb + (size_t)didx.z * 200 + 4 * p));
    dG[3] = __ldg(reinterpret_cast<const uint2*>(Pb + (size_t)didx.w * 200 + 4 * p));
    sG[0] = __ldg(reinterpret_cast<const uint2*>(Pb + (size_t)sidx.x * 200 + 100 + 4 * p));
    sG[1] = __ldg(reinterpret_cast<const uint2*>(Pb + (size_t)sidx.y * 200 + 100 + 4 * p));
    sG[2] = __ldg(reinterpret_cast<const uint2*>(Pb + (size_t)sidx.z * 200 + 100 + 4 * p));
    sG[3] = __ldg(reinterpret_cast<const uint2*>(Pb + (size_t)sidx.w * 200 + 100 + 4 * p));

    uint4 eaq[4];
    const uint4* eap = reinterpret_cast<const uint4*>(g_eah + (size_t)e0 * 8);
    eaq[0] = __ldg(eap + 0);
    eaq[1] = __ldg(eap + 1);
    eaq[2] = __ldg(eap + 2);
    eaq[3] = __ldg(eap + 3);

    int dsts[4] = {didx.x, didx.y, didx.z, didx.w};
    #pragma unroll
    for (int q = 0; q < 4; q++){
      __half2 ea01 = u2h(eaq[q].x), ea23 = u2h(eaq[q].y);
      __half2 ea45 = u2h(eaq[q].z), ea67 = u2h(eaq[q].w);
      __half2 f2 = __hadd2(u2h(dG[q].x), u2h(sG[q].x));
      __half2 s2 = __hadd2(u2h(dG[q].y), u2h(sG[q].y));
      f2 = __hfma2(whf[0], __low2half2(ea01),  f2);  s2 = __hfma2(whs[0], __low2half2(ea01),  s2);
      f2 = __hfma2(whf[1], __high2half2(ea01), f2);  s2 = __hfma2(whs[1], __high2half2(ea01), s2);
      f2 = __hfma2(whf[2], __low2half2(ea23),  f2);  s2 = __hfma2(whs[2], __low2half2(ea23),  s2);
      f2 = __hfma2(whf[3], __high2half2(ea23), f2);  s2 = __hfma2(whs[3], __high2half2(ea23), s2);
      f2 = __hfma2(whf[4], __low2half2(ea45),  f2);  s2 = __hfma2(whs[4], __low2half2(ea45),  s2);
      f2 = __hfma2(whf[5], __high2half2(ea45), f2);  s2 = __hfma2(whs[5], __high2half2(ea45), s2);
      f2 = __hfma2(whf[6], __low2half2(ea67),  f2);  s2 = __hfma2(whs[6], __low2half2(ea67),  s2);
      f2 = __hfma2(whf[7], __high2half2(ea67), f2);  s2 = __hfma2(whs[7], __high2half2(ea67), s2);
      float2 f = __half22float2(f2);
      float2 s = __half22float2(s2);
      float2 m = make_float2(sigm(f.x) * softp(s.x), sigm(f.y) * softp(s.y));
      atomicAdd(reinterpret_cast<float2*>(g_msg + (size_t)dsts[q] * D + c0), m);
    }
  }
}

// ---------------- finalize: residual + ReLU + smem-pooled max/sum ----------------
#define FN_NODES 10
#define FN_SLOTS 16
__global__ void __launch_bounds__(512) finalize_kernel(const float* __restrict__ x, int layer,
                                                       const int* __restrict__ batch){
  __shared__ float s_max[FN_SLOTS][50];
  __shared__ float s_sum[FN_SLOTS][50];
  __shared__ int s_bmin;
  __shared__ unsigned s_used;
  const float* h_in = layer_in(x, layer);
  float* h_out = layer_out(layer);
  int t = threadIdx.x;
  for (int i = t; i < FN_SLOTS * 50; i += 512){
    (&s_max[0][0])[i] = 0.0f; (&s_sum[0][0])[i] = 0.0f;
  }
  if (t == 0){
    int n0 = blockIdx.x * FN_NODES; if (n0 >= NN) n0 = NN - 1;
    s_bmin = batch[n0]; s_used = 0u;
  }
  __syncthreads();
  int bmin = s_bmin;

  if (t < FN_NODES * 50){
    int nl = t / 50, c = t - nl * 50;
    int n = blockIdx.x * FN_NODES + nl;
    if (n < NN){
      size_t i = (size_t)n * D + c;
      float v = fmaxf(g_msg[i] + h_in[i], 0.0f);
      h_out[i] = v;
      g_msg[i] = 0.0f;                       // reset for next layer / next launch
      int b = batch[n];
      int s = b - bmin;
      if ((unsigned)s < FN_SLOTS){
        atomicMax(reinterpret_cast<int*>(&s_max[s][c]), __float_as_int(v));
        atomicAdd(&s_sum[s][c], v);
        if (c == 0) atomicOr(&s_used, 1u << s);
      } else {
        atomicMax(reinterpret_cast<int*>(&g_poolmax[b * D + c]), __float_as_int(v));
        atomicAdd(&g_poolsum[b * D + c], v);
      }
    }
  }
  __syncthreads();
  unsigned used = s_used;
  for (int i = t; i < FN_SLOTS * 50; i += 512){
    int s = i / 50, c = i - s * 50;
    if (used & (1u << s)){
      int b = bmin + s;
      float mv = s_max[s][c];
      if (mv > 0.0f) atomicMax(reinterpret_cast<int*>(&g_poolmax[b * D + c]), __float_as_int(mv));
      float sv = s_sum[s][c];
      if (sv != 0.0f) atomicAdd(&g_poolsum[b * D + c], sv);
    }
  }
}

// accumulate pooled features into enc, re-zero pool buffers for next layer
__global__ void acc_enc_kernel(){
  int i = blockIdx.x * blockDim.x + threadIdx.x;
  if (i >= NG * D) return;
  int b = i / D, c = i - b * D;
  g_enc[b * 100 + c]      += g_poolmax[i];
  g_enc[b * 100 + 50 + c] += g_poolsum[i] / fmaxf((float)g_cnt[b], 1.0f);
  g_poolmax[i] = 0.0f;
  g_poolsum[i] = 0.0f;
}

// ---------------- head: linear + log_softmax; emit [logp | enc] ----------------
__global__ void head_kernel(const float* __restrict__ lw, const float* __restrict__ lb,
                            float* __restrict__ out, int out_size){
  int b = blockIdx.x * blockDim.x + threadIdx.x;
  if (b >= NG) return;
  float e[100];
  #pragma unroll
  for (int k = 0; k < 100; k++) e[k] = g_enc[b * 100 + k];
  float lg[NOUT];
  #pragma unroll
  for (int j = 0; j < NOUT; j++){
    float acc = lb[j];
    #pragma unroll
    for (int k = 0; k < 100; k++) acc += e[k] * lw[j * 100 + k];
    lg[j] = acc;
  }
  float mx = lg[0];
  #pragma unroll
  for (int j = 1; j < NOUT; j++) mx = fmaxf(mx, lg[j]);
  float ss = 0.0f;
  #pragma unroll
  for (int j = 0; j < NOUT; j++) ss += fast_ex2((lg[j] - mx) * kL2E);
  float lse = mx + kLN2 * fast_lg2(ss);
  #pragma unroll
  for (int j = 0; j < NOUT; j++) out[b * NOUT + j] = lg[j] - lse;
  if (out_size >= NG * NOUT + NG * 100){
    #pragma unroll 4
    for (int k = 0; k < 100; k++) out[NG * NOUT + b * 100 + k] = e[k];
  }
}

// ---------------- launch (pure kernel launches; graph-capture safe) ----------------
extern "C" void kernel_launch(void* const* d_in, const int* in_sizes, int n_in,
                              void* d_out, int out_size){
  (void)in_sizes; (void)n_in;
  const float* x  = (const float*)d_in[0];
  const int*   ei = (const int*)  d_in[1];
  const float* ea = (const float*)d_in[2];
  const int*   bt = (const int*)  d_in[3];
  const float* Wf = (const float*)d_in[4];
  const float* bf = (const float*)d_in[5];
  const float* Ws = (const float*)d_in[6];
  const float* bs = (const float*)d_in[7];
  const float* lw = (const float*)d_in[8];
  const float* lb = (const float*)d_in[9];
  float* out = (float*)d_out;

  static bool attr_set = false;
  if (!attr_set){
    cudaFuncSetAttribute(proj_mma_kernel,
                         cudaFuncAttributeMaxDynamicSharedMemorySize, PM_SMEM_BYTES);
    attr_set = true;
  }

  zero_global_bufs<<<128, 256>>>();
  count_kernel<<<(NN + 255) / 256, 256>>>(bt);
  ea_half_kernel<<<1024, 256>>>(ea);

  for (int i = 0; i < 3; i++){
    prep_B_kernel<<<(200 * 60 + 255) / 256, 256>>>(Wf + i * D * DZ, Ws + i * D * DZ);
    proj_mma_kernel<<<(NN + PM_M - 1) / PM_M, 256, PM_SMEM_BYTES>>>(x, i, bf + i * D, bs + i * D);
    edge_kernel<<<2000, 256>>>(ei, Wf + i * D * DZ, Ws + i * D * DZ);
    finalize_kernel<<<(NN + FN_NODES - 1) / FN_NODES, 512>>>(x, i, bt);
    acc_enc_kernel<<<(NG * D + 255) / 256, 256>>>();
  }

  head_kernel<<<(NG + 127) / 128, 128>>>(lw, lb, out, out_size);
}